// round 7
// baseline (speedup 1.0000x reference)
#include <cuda_runtime.h>

// HamiltonianEvolution: out = q_left_n ⊗ (gate*x) ⊗ conj(q_right_n).
// FFT/IFFT pair is an identity (gate constant along the FFT axis) -> the op
// is a per-channel 4x4 linear map. Exact R3 structure (the proven-best body:
// static 2048-block grid, one 8-row tile per block, 2 rows/thread with
// front-batched LDG.128, matrices in smem) + __launch_bounds__(256,5) to
// force the allocator under 51 regs and allow 5 CTAs/SM (40 warps resident).

#define QD 256   // quat_dim
#define NG 64    // channel groups of 4 (float4 lanes)
#define ROWS_PER_BLOCK 8

__global__ __launch_bounds__(256, 5)
void fused_kernel(const float* __restrict__ q_left,
                  const float* __restrict__ q_right,
                  const float* __restrict__ gate,
                  const float4* __restrict__ x,
                  float4* __restrict__ out,
                  int nrows) {
    // sM[i][g] = float4 of matrix entry i=(r*4+c) for channel group g
    __shared__ float4 sM[16][NG];

    const int tid = threadIdx.x;

    // ---- per-block matrix build: thread tid owns channel j = tid ----
    {
        const int j = tid;
        float lw = q_left[0 * QD + j], lx = q_left[1 * QD + j];
        float ly = q_left[2 * QD + j], lz = q_left[3 * QD + j];
        float rw = q_right[0 * QD + j], rx = q_right[1 * QD + j];
        float ry = q_right[2 * QD + j], rz = q_right[3 * QD + j];

        float ln = rsqrtf(lw * lw + lx * lx + ly * ly + lz * lz + 1e-8f);
        lw *= ln; lx *= ln; ly *= ln; lz *= ln;
        float rn = rsqrtf(rw * rw + rx * rx + ry * ry + rz * rz + 1e-8f);
        rw = rw * rn; rx = -rx * rn; ry = -ry * rn; rz = -rz * rn;

        const float g = gate[j];

        // R: p -> p ⊗ rc (rc = conjugated normalized q_right)
        const float R[4][4] = {
            { rw, -rx, -ry, -rz},
            { rx,  rw,  rz, -ry},
            { ry, -rz,  rw,  rx},
            { rz,  ry, -rx,  rw}
        };
        // L: p -> l ⊗ p (l = normalized q_left)
        const float L[4][4] = {
            { lw, -lx, -ly, -lz},
            { lx,  lw, -lz,  ly},
            { ly,  lz,  lw, -lx},
            { lz, -ly,  lx,  lw}
        };

        float* s = reinterpret_cast<float*>(sM);
        #pragma unroll
        for (int r = 0; r < 4; r++) {
            #pragma unroll
            for (int c = 0; c < 4; c++) {
                float acc = 0.0f;
                #pragma unroll
                for (int k = 0; k < 4; k++) acc += L[r][k] * R[k][c];
                s[(r * 4 + c) * QD + j] = g * acc;   // conflict-free write
            }
        }
    }
    __syncthreads();

    // ---- streaming: 2 rows per thread, loads front-batched (MLP=8) ----
    const int grp = tid & 63;   // channel group
    const int sub = tid >> 6;   // 0..3

    const int row0 = blockIdx.x * ROWS_PER_BLOCK + sub;
    const int row1 = row0 + 4;

    const float4* xr0 = x + (size_t)row0 * 256;
    const float4* xr1 = x + (size_t)row1 * 256;

    float4 a0, b0, c0, d0, a1, b1, c1, d1;
    const bool v0 = row0 < nrows;
    const bool v1 = row1 < nrows;
    if (v0) {
        a0 = xr0[0 * 64 + grp];
        b0 = xr0[1 * 64 + grp];
        c0 = xr0[2 * 64 + grp];
        d0 = xr0[3 * 64 + grp];
    }
    if (v1) {
        a1 = xr1[0 * 64 + grp];
        b1 = xr1[1 * 64 + grp];
        c1 = xr1[2 * 64 + grp];
        d1 = xr1[3 * 64 + grp];
    }

    float4* or0 = out + (size_t)row0 * 256;
    float4* or1 = out + (size_t)row1 * 256;

    #pragma unroll
    for (int r = 0; r < 4; r++) {
        const float4 m0 = sM[r * 4 + 0][grp];
        const float4 m1 = sM[r * 4 + 1][grp];
        const float4 m2 = sM[r * 4 + 2][grp];
        const float4 m3 = sM[r * 4 + 3][grp];

        if (v0) {
            float4 o;
            o.x = fmaf(m0.x, a0.x, fmaf(m1.x, b0.x, fmaf(m2.x, c0.x, m3.x * d0.x)));
            o.y = fmaf(m0.y, a0.y, fmaf(m1.y, b0.y, fmaf(m2.y, c0.y, m3.y * d0.y)));
            o.z = fmaf(m0.z, a0.z, fmaf(m1.z, b0.z, fmaf(m2.z, c0.z, m3.z * d0.z)));
            o.w = fmaf(m0.w, a0.w, fmaf(m1.w, b0.w, fmaf(m2.w, c0.w, m3.w * d0.w)));
            or0[r * 64 + grp] = o;
        }
        if (v1) {
            float4 o;
            o.x = fmaf(m0.x, a1.x, fmaf(m1.x, b1.x, fmaf(m2.x, c1.x, m3.x * d1.x)));
            o.y = fmaf(m0.y, a1.y, fmaf(m1.y, b1.y, fmaf(m2.y, c1.y, m3.y * d1.y)));
            o.z = fmaf(m0.z, a1.z, fmaf(m1.z, b1.z, fmaf(m2.z, c1.z, m3.z * d1.z)));
            o.w = fmaf(m0.w, a1.w, fmaf(m1.w, b1.w, fmaf(m2.w, c1.w, m3.w * d1.w)));
            or1[r * 64 + grp] = o;
        }
    }
}

extern "C" void kernel_launch(void* const* d_in, const int* in_sizes, int n_in,
                              void* d_out, int out_size) {
    const float* x    = (const float*)d_in[0];   // (B, T, 1024)
    const float* q_l  = (const float*)d_in[1];   // (4, 256)
    const float* q_r  = (const float*)d_in[2];   // (4, 256)
    const float* gate = (const float*)d_in[3];   // (1,1,1,256)

    const int nrows = in_sizes[0] / 1024;        // B*T
    const int grid = (nrows + ROWS_PER_BLOCK - 1) / ROWS_PER_BLOCK;

    fused_kernel<<<grid, 256>>>(q_l, q_r, gate,
                                reinterpret_cast<const float4*>(x),
                                reinterpret_cast<float4*>(d_out),
                                nrows);
}

// round 8
// speedup vs baseline: 1.4819x; 1.4819x over previous
#include <cuda_runtime.h>

// HamiltonianEvolution: out = q_left_n ⊗ (gate*x) ⊗ conj(q_right_n).
// FFT/IFFT pair is an identity (gate constant along the FFT axis) -> the op
// is a per-channel 4x4 linear map applied to every (b,t) position.
//
// Structure (empirically best across 7 rounds; the kernel is bound by the
// chip LTS throughput cap ~7 TB/s on its 128 MiB of L2 traffic):
//  - 2048 blocks x 256 threads, one 8-row tile per block
//  - per-block rebuild of the 256 composite 4x4 matrices into smem
//  - 2 rows per thread, 8 front-batched LDG.128 (4 KB in flight per warp)
//  - regs = 64 -> 4 CTAs/SM; do NOT force more (spills) or restructure
//    (register blowup) — both were measured regressions.

#define QD 256   // quat_dim
#define NG 64    // channel groups of 4 (float4 lanes)
#define ROWS_PER_BLOCK 8

template <bool CHECK>
__global__ __launch_bounds__(256)
void fused_kernel(const float* __restrict__ q_left,
                  const float* __restrict__ q_right,
                  const float* __restrict__ gate,
                  const float4* __restrict__ x,
                  float4* __restrict__ out,
                  int nrows) {
    // sM[i][g] = float4 of matrix entry i=(r*4+c) for channel group g
    __shared__ float4 sM[16][NG];

    const int tid = threadIdx.x;

    // ---- per-block matrix build: thread tid owns channel j = tid ----
    {
        const int j = tid;
        float lw = q_left[0 * QD + j], lx = q_left[1 * QD + j];
        float ly = q_left[2 * QD + j], lz = q_left[3 * QD + j];
        float rw = q_right[0 * QD + j], rx = q_right[1 * QD + j];
        float ry = q_right[2 * QD + j], rz = q_right[3 * QD + j];

        float ln = rsqrtf(lw * lw + lx * lx + ly * ly + lz * lz + 1e-8f);
        lw *= ln; lx *= ln; ly *= ln; lz *= ln;
        float rn = rsqrtf(rw * rw + rx * rx + ry * ry + rz * rz + 1e-8f);
        rw = rw * rn; rx = -rx * rn; ry = -ry * rn; rz = -rz * rn;

        const float g = gate[j];

        // R: p -> p ⊗ rc (rc = conjugated normalized q_right)
        const float R[4][4] = {
            { rw, -rx, -ry, -rz},
            { rx,  rw,  rz, -ry},
            { ry, -rz,  rw,  rx},
            { rz,  ry, -rx,  rw}
        };
        // L: p -> l ⊗ p (l = normalized q_left)
        const float L[4][4] = {
            { lw, -lx, -ly, -lz},
            { lx,  lw, -lz,  ly},
            { ly,  lz,  lw, -lx},
            { lz, -ly,  lx,  lw}
        };

        float* s = reinterpret_cast<float*>(sM);
        #pragma unroll
        for (int r = 0; r < 4; r++) {
            #pragma unroll
            for (int c = 0; c < 4; c++) {
                float acc = 0.0f;
                #pragma unroll
                for (int k = 0; k < 4; k++) acc += L[r][k] * R[k][c];
                s[(r * 4 + c) * QD + j] = g * acc;   // conflict-free write
            }
        }
    }
    __syncthreads();

    // ---- streaming: 2 rows per thread, loads front-batched (MLP=8) ----
    const int grp = tid & 63;   // channel group
    const int sub = tid >> 6;   // 0..3

    const int row0 = blockIdx.x * ROWS_PER_BLOCK + sub;
    const int row1 = row0 + 4;

    const float4* xr0 = x + (size_t)row0 * 256;
    const float4* xr1 = x + (size_t)row1 * 256;

    float4 a0, b0, c0, d0, a1, b1, c1, d1;
    const bool v0 = !CHECK || (row0 < nrows);
    const bool v1 = !CHECK || (row1 < nrows);
    if (v0) {
        a0 = xr0[0 * 64 + grp];
        b0 = xr0[1 * 64 + grp];
        c0 = xr0[2 * 64 + grp];
        d0 = xr0[3 * 64 + grp];
    }
    if (v1) {
        a1 = xr1[0 * 64 + grp];
        b1 = xr1[1 * 64 + grp];
        c1 = xr1[2 * 64 + grp];
        d1 = xr1[3 * 64 + grp];
    }

    float4* or0 = out + (size_t)row0 * 256;
    float4* or1 = out + (size_t)row1 * 256;

    #pragma unroll
    for (int r = 0; r < 4; r++) {
        const float4 m0 = sM[r * 4 + 0][grp];
        const float4 m1 = sM[r * 4 + 1][grp];
        const float4 m2 = sM[r * 4 + 2][grp];
        const float4 m3 = sM[r * 4 + 3][grp];

        if (v0) {
            float4 o;
            o.x = fmaf(m0.x, a0.x, fmaf(m1.x, b0.x, fmaf(m2.x, c0.x, m3.x * d0.x)));
            o.y = fmaf(m0.y, a0.y, fmaf(m1.y, b0.y, fmaf(m2.y, c0.y, m3.y * d0.y)));
            o.z = fmaf(m0.z, a0.z, fmaf(m1.z, b0.z, fmaf(m2.z, c0.z, m3.z * d0.z)));
            o.w = fmaf(m0.w, a0.w, fmaf(m1.w, b0.w, fmaf(m2.w, c0.w, m3.w * d0.w)));
            or0[r * 64 + grp] = o;
        }
        if (v1) {
            float4 o;
            o.x = fmaf(m0.x, a1.x, fmaf(m1.x, b1.x, fmaf(m2.x, c1.x, m3.x * d1.x)));
            o.y = fmaf(m0.y, a1.y, fmaf(m1.y, b1.y, fmaf(m2.y, c1.y, m3.y * d1.y)));
            o.z = fmaf(m0.z, a1.z, fmaf(m1.z, b1.z, fmaf(m2.z, c1.z, m3.z * d1.z)));
            o.w = fmaf(m0.w, a1.w, fmaf(m1.w, b1.w, fmaf(m2.w, c1.w, m3.w * d1.w)));
            or1[r * 64 + grp] = o;
        }
    }
}

extern "C" void kernel_launch(void* const* d_in, const int* in_sizes, int n_in,
                              void* d_out, int out_size) {
    const float* x    = (const float*)d_in[0];   // (B, T, 1024)
    const float* q_l  = (const float*)d_in[1];   // (4, 256)
    const float* q_r  = (const float*)d_in[2];   // (4, 256)
    const float* gate = (const float*)d_in[3];   // (1,1,1,256)

    const int nrows = in_sizes[0] / 1024;        // B*T = 16384
    const int grid = (nrows + ROWS_PER_BLOCK - 1) / ROWS_PER_BLOCK;

    if (nrows % ROWS_PER_BLOCK == 0) {
        fused_kernel<false><<<grid, 256>>>(q_l, q_r, gate,
                                           reinterpret_cast<const float4*>(x),
                                           reinterpret_cast<float4*>(d_out),
                                           nrows);
    } else {
        fused_kernel<true><<<grid, 256>>>(q_l, q_r, gate,
                                          reinterpret_cast<const float4*>(x),
                                          reinterpret_cast<float4*>(d_out),
                                          nrows);
    }
}